// round 1
// baseline (speedup 1.0000x reference)
#include <cuda_runtime.h>
#include <math.h>

// Problem constants
#define BB   8
#define SS   1024
#define EE   1024
#define HH   16
#define HDD  64
#define FF   4096
#define MR   (BB*SS)      // 8192 rows

// -------- scratch (static device globals; no runtime allocation) --------
__device__ float g_qkv[(size_t)MR * 3 * EE];   // 96 MB
__device__ float g_ctx[(size_t)MR * EE];       // 32 MB
__device__ float g_t1 [(size_t)MR * EE];       // 32 MB
__device__ float g_h  [(size_t)MR * EE];       // 32 MB
__device__ float g_ffa[(size_t)MR * FF];       // 128 MB
__device__ float g_t2 [(size_t)MR * EE];       // 32 MB
__device__ float g_kadd[MR];                   // am ? 1 : 0   (per key: additive mask contribution)
__device__ float g_kneg[MR];                   // question_mask ? 1 : 0 (key fully masked)

// ======================= mask precompute =======================
__global__ void mask_kernel(const int* __restrict__ am, const int* __restrict__ tt) {
    int i = blockIdx.x * 256 + threadIdx.x;
    if (i >= MR) return;
    bool a  = (am[i] != 0);
    bool qm = (tt[i] == 1) || (!a) || ((i & (SS - 1)) == 0);  // first pos always masked
    g_kadd[i] = a  ? 1.f : 0.f;
    g_kneg[i] = qm ? 1.f : 0.f;
}

// ======================= SGEMM: C = A[M,K] @ W[K,N] + bias (+res) (+gelu) ==========
// 128x128 block, BK=16, 256 threads, 8x8 microtile.
__global__ __launch_bounds__(256) void gemm_kernel(
    const float* __restrict__ A, const float* __restrict__ W,
    const float* __restrict__ bias, const float* __restrict__ res,
    float* __restrict__ C, int M, int N, int K, int act)
{
    __shared__ float As[16][132];   // [k][m], padded
    __shared__ float Bs[16][128];   // [k][n]

    int tid = threadIdx.x;
    int bm = blockIdx.y * 128;
    int bn = blockIdx.x * 128;
    int ty = tid >> 4;      // 0..15 -> m rows ty*8..+7
    int tx = tid & 15;      // 0..15 -> n cols tx*8..+7

    float acc[8][8];
#pragma unroll
    for (int i = 0; i < 8; i++)
#pragma unroll
        for (int j = 0; j < 8; j++) acc[i][j] = 0.f;

    for (int k0 = 0; k0 < K; k0 += 16) {
#pragma unroll
        for (int i = 0; i < 8; i++) {
            int idx = i * 256 + tid;
            int r = idx >> 4, c = idx & 15;
            As[c][r] = A[(size_t)(bm + r) * K + k0 + c];
        }
#pragma unroll
        for (int i = 0; i < 8; i++) {
            int idx = i * 256 + tid;
            int r = idx >> 7, c = idx & 127;
            Bs[r][c] = W[(size_t)(k0 + r) * N + bn + c];
        }
        __syncthreads();
#pragma unroll
        for (int kk = 0; kk < 16; kk++) {
            float4 a0 = *reinterpret_cast<const float4*>(&As[kk][ty * 8]);
            float4 a1 = *reinterpret_cast<const float4*>(&As[kk][ty * 8 + 4]);
            float4 b0 = *reinterpret_cast<const float4*>(&Bs[kk][tx * 8]);
            float4 b1 = *reinterpret_cast<const float4*>(&Bs[kk][tx * 8 + 4]);
            float ar[8] = {a0.x, a0.y, a0.z, a0.w, a1.x, a1.y, a1.z, a1.w};
            float br[8] = {b0.x, b0.y, b0.z, b0.w, b1.x, b1.y, b1.z, b1.w};
#pragma unroll
            for (int i = 0; i < 8; i++)
#pragma unroll
                for (int j = 0; j < 8; j++)
                    acc[i][j] = fmaf(ar[i], br[j], acc[i][j]);
        }
        __syncthreads();
    }

#pragma unroll
    for (int i = 0; i < 8; i++) {
        int r = bm + ty * 8 + i;
#pragma unroll
        for (int j = 0; j < 8; j++) {
            int cn = bn + tx * 8 + j;
            float v = acc[i][j] + bias[cn];
            if (res) v += res[(size_t)r * N + cn];
            if (act == 1) v = 0.5f * v * (1.0f + erff(v * 0.70710678118654752f));
            C[(size_t)r * N + cn] = v;
        }
    }
}

// ======================= Flash attention =======================
// grid: (S/64, H, B), 256 threads. BQ=BK=64, HD=64.
// smem: sQ[64*65] | sK[64*65] (aliased by sP) | sV[64*65]
__global__ __launch_bounds__(256) void attn_kernel(
    const float* __restrict__ QKV, float* __restrict__ CTX)
{
    extern __shared__ float sm[];
    float* sQ = sm;
    float* sK = sm + 64 * 65;
    float* sV = sm + 2 * 64 * 65;
    float* sP = sK;  // alias: P tile overwrites K tile after scores done
    __shared__ float sAdd[64], sNeg[64], sAmq[64];

    int tid = threadIdx.x;
    int b = blockIdx.z, h = blockIdx.y, q0 = blockIdx.x * 64;

    const float* Qb = QKV + (size_t)b * SS * 3072 + h * 64;
    const float* Kb = Qb + 1024;
    const float* Vb = Qb + 2048;

    // load Q tile
    for (int i = tid; i < 64 * 64; i += 256) {
        int r = i >> 6, c = i & 63;
        sQ[r * 65 + c] = Qb[(size_t)(q0 + r) * 3072 + c];
    }
    for (int i = tid; i < 64; i += 256) sAmq[i] = g_kadd[b * SS + q0 + i];
    __syncthreads();

    int qg = tid >> 4;   // 0..15 -> q rows qg*4..+3
    int cg = tid & 15;   // 0..15 -> k/d cols cg*4..+3

    float amq[4];
#pragma unroll
    for (int i = 0; i < 4; i++) amq[i] = sAmq[qg * 4 + i];

    float m[4], l[4], o[4][4];
#pragma unroll
    for (int i = 0; i < 4; i++) {
        m[i] = -INFINITY; l[i] = 0.f;
#pragma unroll
        for (int j = 0; j < 4; j++) o[i][j] = 0.f;
    }

    const float* qp[4];
#pragma unroll
    for (int i = 0; i < 4; i++) qp[i] = &sQ[(qg * 4 + i) * 65];

    for (int k0 = 0; k0 < SS; k0 += 64) {
        __syncthreads();  // previous tile's P@V reads done before overwrite
        for (int i = tid; i < 64 * 64; i += 256) {
            int r = i >> 6, c = i & 63;
            sK[r * 65 + c] = Kb[(size_t)(k0 + r) * 3072 + c];
            sV[r * 65 + c] = Vb[(size_t)(k0 + r) * 3072 + c];
        }
        for (int i = tid; i < 64; i += 256) {
            sAdd[i] = g_kadd[b * SS + k0 + i];
            sNeg[i] = g_kneg[b * SS + k0 + i];
        }
        __syncthreads();

        // ---- scores: sc[i][j] = Q[qi] . K[kj] ----
        float sc[4][4];
#pragma unroll
        for (int i = 0; i < 4; i++)
#pragma unroll
            for (int j = 0; j < 4; j++) sc[i][j] = 0.f;

        const float* kp[4];
#pragma unroll
        for (int j = 0; j < 4; j++) kp[j] = &sK[(cg * 4 + j) * 65];

#pragma unroll 8
        for (int d = 0; d < 64; d++) {
            float a0 = qp[0][d], a1 = qp[1][d], a2 = qp[2][d], a3 = qp[3][d];
            float b0 = kp[0][d], b1 = kp[1][d], b2 = kp[2][d], b3 = kp[3][d];
            sc[0][0] = fmaf(a0, b0, sc[0][0]); sc[0][1] = fmaf(a0, b1, sc[0][1]);
            sc[0][2] = fmaf(a0, b2, sc[0][2]); sc[0][3] = fmaf(a0, b3, sc[0][3]);
            sc[1][0] = fmaf(a1, b0, sc[1][0]); sc[1][1] = fmaf(a1, b1, sc[1][1]);
            sc[1][2] = fmaf(a1, b2, sc[1][2]); sc[1][3] = fmaf(a1, b3, sc[1][3]);
            sc[2][0] = fmaf(a2, b0, sc[2][0]); sc[2][1] = fmaf(a2, b1, sc[2][1]);
            sc[2][2] = fmaf(a2, b2, sc[2][2]); sc[2][3] = fmaf(a2, b3, sc[2][3]);
            sc[3][0] = fmaf(a3, b0, sc[3][0]); sc[3][1] = fmaf(a3, b1, sc[3][1]);
            sc[3][2] = fmaf(a3, b2, sc[3][2]); sc[3][3] = fmaf(a3, b3, sc[3][3]);
        }

        // ---- mask ----
        float kadd[4], kneg[4];
#pragma unroll
        for (int j = 0; j < 4; j++) { kadd[j] = sAdd[cg * 4 + j]; kneg[j] = sNeg[cg * 4 + j]; }
#pragma unroll
        for (int i = 0; i < 4; i++)
#pragma unroll
            for (int j = 0; j < 4; j++) {
                float v = sc[i][j] * 0.125f + amq[i] * kadd[j];
                sc[i][j] = (kneg[j] != 0.f) ? -1e30f : v;
            }

        // ---- online softmax (reduce across 16 lanes sharing the query rows) ----
        float mt[4], lt[4], alpha[4];
#pragma unroll
        for (int i = 0; i < 4; i++) {
            mt[i] = fmaxf(fmaxf(sc[i][0], sc[i][1]), fmaxf(sc[i][2], sc[i][3]));
#pragma unroll
            for (int off = 8; off > 0; off >>= 1)
                mt[i] = fmaxf(mt[i], __shfl_xor_sync(0xffffffffu, mt[i], off, 16));
            float mn = fmaxf(m[i], mt[i]);
            alpha[i] = __expf(m[i] - mn);
            m[i] = mn;
            lt[i] = 0.f;
#pragma unroll
            for (int j = 0; j < 4; j++) {
                float p = __expf(sc[i][j] - mn);
                sc[i][j] = p;
                lt[i] += p;
            }
#pragma unroll
            for (int off = 8; off > 0; off >>= 1)
                lt[i] += __shfl_xor_sync(0xffffffffu, lt[i], off, 16);
            l[i] = l[i] * alpha[i] + lt[i];
#pragma unroll
            for (int j = 0; j < 4; j++) o[i][j] *= alpha[i];
        }

        __syncthreads();  // everyone done reading sK
        // write P tile (aliases sK)
#pragma unroll
        for (int i = 0; i < 4; i++)
#pragma unroll
            for (int j = 0; j < 4; j++)
                sP[(qg * 4 + i) * 65 + cg * 4 + j] = sc[i][j];
        __syncthreads();

        // ---- O += P @ V  (dims dj = cg*4+j) ----
        const float* pp[4];
#pragma unroll
        for (int i = 0; i < 4; i++) pp[i] = &sP[(qg * 4 + i) * 65];
#pragma unroll 8
        for (int k = 0; k < 64; k++) {
            const float* vp = &sV[k * 65 + cg * 4];
            float v0 = vp[0], v1 = vp[1], v2 = vp[2], v3 = vp[3];
            float p0 = pp[0][k], p1 = pp[1][k], p2 = pp[2][k], p3 = pp[3][k];
            o[0][0] = fmaf(p0, v0, o[0][0]); o[0][1] = fmaf(p0, v1, o[0][1]);
            o[0][2] = fmaf(p0, v2, o[0][2]); o[0][3] = fmaf(p0, v3, o[0][3]);
            o[1][0] = fmaf(p1, v0, o[1][0]); o[1][1] = fmaf(p1, v1, o[1][1]);
            o[1][2] = fmaf(p1, v2, o[1][2]); o[1][3] = fmaf(p1, v3, o[1][3]);
            o[2][0] = fmaf(p2, v0, o[2][0]); o[2][1] = fmaf(p2, v1, o[2][1]);
            o[2][2] = fmaf(p2, v2, o[2][2]); o[2][3] = fmaf(p2, v3, o[2][3]);
            o[3][0] = fmaf(p3, v0, o[3][0]); o[3][1] = fmaf(p3, v1, o[3][1]);
            o[3][2] = fmaf(p3, v2, o[3][2]); o[3][3] = fmaf(p3, v3, o[3][3]);
        }
    }

    // ---- epilogue: normalize and write ctx[b, q, h*64 + d] ----
#pragma unroll
    for (int i = 0; i < 4; i++) {
        float inv = 1.f / l[i];
        size_t row = (size_t)(b * SS + q0 + qg * 4 + i);
#pragma unroll
        for (int j = 0; j < 4; j++)
            CTX[row * EE + h * 64 + cg * 4 + j] = o[i][j] * inv;
    }
}

// ======================= LayerNorm (E=1024, one block per row) =======================
__global__ __launch_bounds__(256) void ln_kernel(
    const float* __restrict__ in, const float* __restrict__ w,
    const float* __restrict__ b, float* __restrict__ out)
{
    int row = blockIdx.x;
    const float* x = in + (size_t)row * EE;
    int tid = threadIdx.x;

    float v[4], s = 0.f, sq = 0.f;
#pragma unroll
    for (int i = 0; i < 4; i++) {
        v[i] = x[tid + i * 256];
        s += v[i];
        sq += v[i] * v[i];
    }
#pragma unroll
    for (int off = 16; off > 0; off >>= 1) {
        s  += __shfl_xor_sync(0xffffffffu, s,  off);
        sq += __shfl_xor_sync(0xffffffffu, sq, off);
    }
    __shared__ float ss[8], ssq[8];
    if ((tid & 31) == 0) { ss[tid >> 5] = s; ssq[tid >> 5] = sq; }
    __syncthreads();
    float ts = 0.f, tsq = 0.f;
#pragma unroll
    for (int wi = 0; wi < 8; wi++) { ts += ss[wi]; tsq += ssq[wi]; }
    float mean = ts * (1.f / EE);
    float var = tsq * (1.f / EE) - mean * mean;
    float rstd = rsqrtf(var + 1e-12f);
    float* y = out + (size_t)row * EE;
#pragma unroll
    for (int i = 0; i < 4; i++) {
        int c = tid + i * 256;
        y[c] = (v[i] - mean) * rstd * w[c] + b[c];
    }
}

// ======================= launch =======================
extern "C" void kernel_launch(void* const* d_in, const int* in_sizes, int n_in,
                              void* d_out, int out_size)
{
    const float* x      = (const float*)d_in[0];
    const int*   am     = (const int*)d_in[1];
    const int*   tt     = (const int*)d_in[2];
    const float* w_qkv  = (const float*)d_in[3];
    const float* b_qkv  = (const float*)d_in[4];
    const float* w_out  = (const float*)d_in[5];
    const float* b_outp = (const float*)d_in[6];
    const float* ln_w   = (const float*)d_in[7];
    const float* ln_b   = (const float*)d_in[8];
    const float* w_in   = (const float*)d_in[9];
    const float* b_in   = (const float*)d_in[10];
    const float* w_ffo  = (const float*)d_in[11];
    const float* b_ffo  = (const float*)d_in[12];
    float* out = (float*)d_out;

    float *qkv, *ctx, *t1, *hb, *ffa, *t2;
    cudaGetSymbolAddress((void**)&qkv, g_qkv);
    cudaGetSymbolAddress((void**)&ctx, g_ctx);
    cudaGetSymbolAddress((void**)&t1,  g_t1);
    cudaGetSymbolAddress((void**)&hb,  g_h);
    cudaGetSymbolAddress((void**)&ffa, g_ffa);
    cudaGetSymbolAddress((void**)&t2,  g_t2);

    const int ATTN_SMEM = 3 * 64 * 65 * (int)sizeof(float);  // 49920 B dynamic
    cudaFuncSetAttribute(attn_kernel, cudaFuncAttributeMaxDynamicSharedMemorySize, ATTN_SMEM);

    // 1. masks
    mask_kernel<<<MR / 256, 256>>>(am, tt);

    // 2. QKV projection: [8192,1024] @ [1024,3072]
    gemm_kernel<<<dim3(3 * EE / 128, MR / 128), 256>>>(x, w_qkv, b_qkv, nullptr, qkv,
                                                       MR, 3 * EE, EE, 0);
    // 3. attention
    attn_kernel<<<dim3(SS / 64, HH, BB), 256, ATTN_SMEM>>>(qkv, ctx);

    // 4. out projection + residual x
    gemm_kernel<<<dim3(EE / 128, MR / 128), 256>>>(ctx, w_out, b_outp, x, t1,
                                                   MR, EE, EE, 0);
    // 5. LN -> h
    ln_kernel<<<MR, 256>>>(t1, ln_w, ln_b, hb);

    // 6. FFN in + exact GELU
    gemm_kernel<<<dim3(FF / 128, MR / 128), 256>>>(hb, w_in, b_in, nullptr, ffa,
                                                   MR, FF, EE, 1);
    // 7. FFN out + residual h
    gemm_kernel<<<dim3(EE / 128, MR / 128), 256>>>(ffa, w_ffo, b_ffo, hb, t2,
                                                   MR, EE, FF, 0);
    // 8. LN -> out
    ln_kernel<<<MR, 256>>>(t2, ln_w, ln_b, out);
}

// round 3
// speedup vs baseline: 1.8173x; 1.8173x over previous
#include <cuda_runtime.h>
#include <math.h>
#include <stdint.h>

// Problem constants
#define BB   8
#define SS   1024
#define EE   1024
#define HH   16
#define FF   4096
#define MR   (BB*SS)      // 8192 rows

// -------- scratch (static device globals; no runtime allocation) --------
__device__ float g_qkv[(size_t)MR * 3 * EE];
__device__ float g_ctx[(size_t)MR * EE];
__device__ float g_t1 [(size_t)MR * EE];
__device__ float g_h  [(size_t)MR * EE];
__device__ float g_ffa[(size_t)MR * FF];
__device__ float g_t2 [(size_t)MR * EE];
__device__ float g_kadd[MR];
__device__ float g_kneg[MR];
// transposed weights (tf32-rounded), [N,K] K-major
__device__ float g_wqkvT[(size_t)3 * EE * EE];
__device__ float g_woutT[(size_t)EE * EE];
__device__ float g_winT [(size_t)FF * EE];
__device__ float g_wffoT[(size_t)EE * FF];

// ======================= PTX helpers (all sm_80-baseline, compile on compute_103) ==========
__device__ __forceinline__ uint32_t smem_u32(const void* p) {
    uint32_t a;
    asm("{ .reg .u64 t; cvta.to.shared.u64 t, %1; cvt.u32.u64 %0, t; }"
        : "=r"(a) : "l"(p));
    return a;
}
__device__ __forceinline__ void cp16(uint32_t dst, const void* src) {
    asm volatile("cp.async.cg.shared.global [%0], [%1], 16;" :: "r"(dst), "l"(src));
}
#define CP_COMMIT() asm volatile("cp.async.commit_group;" ::: "memory")

__device__ __forceinline__ void ldsm4(uint32_t& r0, uint32_t& r1, uint32_t& r2, uint32_t& r3,
                                      uint32_t addr) {
    asm volatile("ldmatrix.sync.aligned.m8n8.x4.shared.b16 {%0,%1,%2,%3}, [%4];"
                 : "=r"(r0), "=r"(r1), "=r"(r2), "=r"(r3) : "r"(addr));
}
__device__ __forceinline__ uint32_t f2tf32(uint32_t x) {
    uint32_t y;
    asm("cvt.rna.tf32.f32 %0, %1;" : "=r"(y) : "f"(__uint_as_float(x)));
    return y;
}
__device__ __forceinline__ void mma_tf32(float* c, const uint32_t* a, uint32_t b0, uint32_t b1) {
    asm volatile(
        "mma.sync.aligned.m16n8k8.row.col.f32.tf32.tf32.f32 "
        "{%0,%1,%2,%3}, {%4,%5,%6,%7}, {%8,%9}, {%0,%1,%2,%3};"
        : "+f"(c[0]), "+f"(c[1]), "+f"(c[2]), "+f"(c[3])
        : "r"(a[0]), "r"(a[1]), "r"(a[2]), "r"(a[3]), "r"(b0), "r"(b1));
}

// ======================= weight transpose + tf32 round =======================
__global__ void transpose_kernel(const float* __restrict__ W, float* __restrict__ WT,
                                 int K, int N) {
    __shared__ float t[32][33];
    int n0 = blockIdx.x * 32, k0 = blockIdx.y * 32;
    int tx = threadIdx.x, ty = threadIdx.y;
#pragma unroll
    for (int i = 0; i < 32; i += 8)
        t[ty + i][tx] = W[(size_t)(k0 + ty + i) * N + n0 + tx];
    __syncthreads();
#pragma unroll
    for (int i = 0; i < 32; i += 8) {
        float v = t[tx][ty + i];
        uint32_t b;
        asm("cvt.rna.tf32.f32 %0, %1;" : "=r"(b) : "f"(v));
        WT[(size_t)(n0 + ty + i) * K + k0 + tx] = __uint_as_float(b);
    }
}

// ======================= mask precompute =======================
__global__ void mask_kernel(const int* __restrict__ am, const int* __restrict__ tt) {
    int i = blockIdx.x * 256 + threadIdx.x;
    if (i >= MR) return;
    bool a  = (am[i] != 0);
    bool qm = (tt[i] == 1) || (!a) || ((i & (SS - 1)) == 0);
    g_kadd[i] = a  ? 1.f : 0.f;
    g_kneg[i] = qm ? 1.f : 0.f;
}

// ======================= tf32 tensor-core GEMM (mma.sync) =======================
// C[M,N] = A[M,K] @ BT[N,K]^T (+bias) (+res) (+gelu)
#define GBM 128
#define GBN 128
#define GBK 32
#define GSTAGES 4
#define GSTAGE_A (GBM * GBK * 4)            // 16 KB
#define GSTAGE_BYTES (2 * GSTAGE_A)         // 32 KB
#define GEMM_SMEM_DYN (GSTAGES * GSTAGE_BYTES)

__global__ __launch_bounds__(256, 1) void mma_gemm(
    const float* __restrict__ A, const float* __restrict__ BT,
    const float* __restrict__ bias, const float* __restrict__ res,
    float* __restrict__ C, int M, int N, int K, int act)
{
    extern __shared__ char dyn_smem[];
    uint32_t sbase = smem_u32(dyn_smem);
    int tid = threadIdx.x, lane = tid & 31, wid = tid >> 5;
    int wm = wid & 3, wn = wid >> 2;            // warp tile: rows wm*32, cols wn*64
    int bm = blockIdx.y * GBM, bn = blockIdx.x * GBN;

    float c[2][8][4];
#pragma unroll
    for (int mi = 0; mi < 2; mi++)
#pragma unroll
        for (int j = 0; j < 8; j++)
#pragma unroll
            for (int q = 0; q < 4; q++) c[mi][j][q] = 0.f;

    int T = K / GBK;

    auto load_tile = [&](int t, int s) {
        int k0 = t * GBK;
        uint32_t sA = sbase + s * GSTAGE_BYTES;
        uint32_t sB = sA + GSTAGE_A;
#pragma unroll
        for (int i = 0; i < 4; i++) {            // A: 1024 granules / 256 thr
            int g = tid + i * 256;
            int row = g >> 3, ch = g & 7;
            cp16(sA + row * 128 + ((ch ^ (row & 7)) << 4),
                 A + (size_t)(bm + row) * K + k0 + ch * 4);
        }
#pragma unroll
        for (int i = 0; i < 4; i++) {            // B
            int g = tid + i * 256;
            int row = g >> 3, ch = g & 7;
            cp16(sB + row * 128 + ((ch ^ (row & 7)) << 4),
                 BT + (size_t)(bn + row) * K + k0 + ch * 4);
        }
    };

    load_tile(0, 0); CP_COMMIT();
    load_tile(1, 1); CP_COMMIT();
    load_tile(2, 2); CP_COMMIT();

    for (int t = 0; t < T; t++) {
        asm volatile("cp.async.wait_group 2;" ::: "memory");
        __syncthreads();
        if (t + 3 < T) load_tile(t + 3, (t + 3) & 3);
        CP_COMMIT();

        int s = t & 3;
        uint32_t sA = sbase + s * GSTAGE_BYTES;
        uint32_t sB = sA + GSTAGE_A;

#pragma unroll
        for (int p = 0; p < 2; p++) {            // two halves of BK=32 (2 ksteps each)
            uint32_t b[8][4];
#pragma unroll
            for (int j = 0; j < 8; j++) {
                int r = wn * 64 + j * 8 + (lane & 7);
                int ch = p * 4 + (lane >> 3);
                ldsm4(b[j][0], b[j][1], b[j][2], b[j][3],
                      sB + r * 128 + ((ch ^ (r & 7)) << 4));
            }
            uint32_t a[2][2][4];
#pragma unroll
            for (int mi = 0; mi < 2; mi++)
#pragma unroll
                for (int kk = 0; kk < 2; kk++) {
                    int ks = p * 2 + kk;
                    int r = wm * 32 + mi * 16 + ((lane >> 3) & 1) * 8 + (lane & 7);
                    int ch = ks * 2 + (lane >> 4);
                    ldsm4(a[mi][kk][0], a[mi][kk][1], a[mi][kk][2], a[mi][kk][3],
                          sA + r * 128 + ((ch ^ (r & 7)) << 4));
#pragma unroll
                    for (int q = 0; q < 4; q++) a[mi][kk][q] = f2tf32(a[mi][kk][q]);
                }
#pragma unroll
            for (int kk = 0; kk < 2; kk++)
#pragma unroll
                for (int mi = 0; mi < 2; mi++)
#pragma unroll
                    for (int j = 0; j < 8; j++)
                        mma_tf32(c[mi][j], a[mi][kk], b[j][2 * kk], b[j][2 * kk + 1]);
        }
    }

    // ---- epilogue: fused bias / residual / GELU, float2 stores ----
#pragma unroll
    for (int mi = 0; mi < 2; mi++) {
        int r0 = bm + wm * 32 + mi * 16 + (lane >> 2);
#pragma unroll
        for (int half = 0; half < 2; half++) {
            int r = r0 + half * 8;
            float* Crow = C + (size_t)r * N;
            const float* Rrow = res ? res + (size_t)r * N : nullptr;
#pragma unroll
            for (int j = 0; j < 8; j++) {
                int col = bn + wn * 64 + j * 8 + (lane & 3) * 2;
                float v0 = c[mi][j][half * 2 + 0] + bias[col];
                float v1 = c[mi][j][half * 2 + 1] + bias[col + 1];
                if (Rrow) { v0 += Rrow[col]; v1 += Rrow[col + 1]; }
                if (act) {
                    v0 = 0.5f * v0 * (1.0f + erff(v0 * 0.70710678118654752f));
                    v1 = 0.5f * v1 * (1.0f + erff(v1 * 0.70710678118654752f));
                }
                *(float2*)(Crow + col) = make_float2(v0, v1);
            }
        }
    }
}

// ======================= Flash attention (fp32 SIMT) =======================
__global__ __launch_bounds__(256) void attn_kernel(
    const float* __restrict__ QKV, float* __restrict__ CTX)
{
    extern __shared__ float sm[];
    float* sQ = sm;
    float* sK = sm + 64 * 65;
    float* sV = sm + 2 * 64 * 65;
    float* sP = sK;
    __shared__ float sAdd[64], sNeg[64], sAmq[64];

    int tid = threadIdx.x;
    int b = blockIdx.z, h = blockIdx.y, q0 = blockIdx.x * 64;

    const float* Qb = QKV + (size_t)b * SS * 3072 + h * 64;
    const float* Kb = Qb + 1024;
    const float* Vb = Qb + 2048;

    for (int i = tid; i < 64 * 64; i += 256) {
        int r = i >> 6, c = i & 63;
        sQ[r * 65 + c] = Qb[(size_t)(q0 + r) * 3072 + c];
    }
    for (int i = tid; i < 64; i += 256) sAmq[i] = g_kadd[b * SS + q0 + i];
    __syncthreads();

    int qg = tid >> 4;
    int cg = tid & 15;

    float amq[4];
#pragma unroll
    for (int i = 0; i < 4; i++) amq[i] = sAmq[qg * 4 + i];

    float m[4], l[4], o[4][4];
#pragma unroll
    for (int i = 0; i < 4; i++) {
        m[i] = -INFINITY; l[i] = 0.f;
#pragma unroll
        for (int j = 0; j < 4; j++) o[i][j] = 0.f;
    }

    const float* qp[4];
#pragma unroll
    for (int i = 0; i < 4; i++) qp[i] = &sQ[(qg * 4 + i) * 65];

    for (int k0 = 0; k0 < SS; k0 += 64) {
        __syncthreads();
        for (int i = tid; i < 64 * 64; i += 256) {
            int r = i >> 6, c = i & 63;
            sK[r * 65 + c] = Kb[(size_t)(k0 + r) * 3072 + c];
            sV[r * 65 + c] = Vb[(size_t)(k0 + r) * 3072 + c];
        }
        for (int i = tid; i < 64; i += 256) {
            sAdd[i] = g_kadd[b * SS + k0 + i];
            sNeg[i] = g_kneg[b * SS + k0 + i];
        }
        __syncthreads();

        float sc[4][4];
#pragma unroll
        for (int i = 0; i < 4; i++)
#pragma unroll
            for (int j = 0; j < 4; j++) sc[i][j] = 0.f;

        const float* kp[4];
#pragma unroll
        for (int j = 0; j < 4; j++) kp[j] = &sK[(cg * 4 + j) * 65];

#pragma unroll 8
        for (int d = 0; d < 64; d++) {
            float a0 = qp[0][d], a1 = qp[1][d], a2 = qp[2][d], a3 = qp[3][d];
            float b0 = kp[0][d], b1 = kp[1][d], b2 = kp[2][d], b3 = kp[3][d];
            sc[0][0] = fmaf(a0, b0, sc[0][0]); sc[0][1] = fmaf(a0, b1, sc[0][1]);
            sc[0][2] = fmaf(a0, b2, sc[0][2]); sc[0][3] = fmaf(a0, b3, sc[0][3]);
            sc[1][0] = fmaf(a1, b0, sc[1][0]); sc[1][1] = fmaf(a1, b1, sc[1][1]);
            sc[1][2] = fmaf(a1, b2, sc[1][2]); sc[1][3] = fmaf(a1, b3, sc[1][3]);
            sc[2][0] = fmaf(a2, b0, sc[2][0]); sc[2][1] = fmaf(a2, b1, sc[2][1]);
            sc[2][2] = fmaf(a2, b2, sc[2][2]); sc[2][3] = fmaf(a2, b3, sc[2][3]);
            sc[3][0] = fmaf(a3, b0, sc[3][0]); sc[3][1] = fmaf(a3, b1, sc[3][1]);
            sc[3][2] = fmaf(a3, b2, sc[3][2]); sc[3][3] = fmaf(a3, b3, sc[3][3]);
        }

        float kadd[4], kneg[4];
#pragma unroll
        for (int j = 0; j < 4; j++) { kadd[j] = sAdd[cg * 4 + j]; kneg[j] = sNeg[cg * 4 + j]; }
#pragma unroll
        for (int i = 0; i < 4; i++)
#pragma unroll
            for (int j = 0; j < 4; j++) {
                float v = sc[i][j] * 0.125f + amq[i] * kadd[j];
                sc[i][j] = (kneg[j] != 0.f) ? -1e30f : v;
            }

        float mt[4], lt[4], alpha[4];
#pragma unroll
        for (int i = 0; i < 4; i++) {
            mt[i] = fmaxf(fmaxf(sc[i][0], sc[i][1]), fmaxf(sc[i][2], sc[i][3]));
#pragma unroll
            for (int off = 8; off > 0; off >>= 1)
                mt[i] = fmaxf(mt[i], __shfl_xor_sync(0xffffffffu, mt[i], off, 16));
            float mn = fmaxf(m[i], mt[i]);
            alpha[i] = __expf(m[i] - mn);
            m[i] = mn;
            lt[i] = 0.f;
#pragma unroll
            for (int j = 0; j < 4; j++) {
                float p = __expf(sc[i][j] - mn);
                sc[i][j] = p;
                lt[i] += p;
            }
#pragma unroll
            for (int off = 8; off > 0; off >>= 1)
                lt[i] += __shfl_xor_sync(0xffffffffu, lt[i], off, 16);
            l[i] = l[i] * alpha[i] + lt[i];
#pragma unroll
            for (int j = 0; j < 4; j++) o[i][j] *= alpha[i];
        }

        __syncthreads();
#pragma unroll
        for (int i = 0; i < 4; i++)
#pragma unroll
            for (int j = 0; j < 4; j++)
                sP[(qg * 4 + i) * 65 + cg * 4 + j] = sc[i][j];
        __syncthreads();

        const float* pp[4];
#pragma unroll
        for (int i = 0; i < 4; i++) pp[i] = &sP[(qg * 4 + i) * 65];
#pragma unroll 8
        for (int k = 0; k < 64; k++) {
            const float* vp = &sV[k * 65 + cg * 4];
            float v0 = vp[0], v1 = vp[1], v2 = vp[2], v3 = vp[3];
            float p0 = pp[0][k], p1 = pp[1][k], p2 = pp[2][k], p3 = pp[3][k];
            o[0][0] = fmaf(p0, v0, o[0][0]); o[0][1] = fmaf(p0, v1, o[0][1]);
            o[0][2] = fmaf(p0, v2, o[0][2]); o[0][3] = fmaf(p0, v3, o[0][3]);
            o[1][0] = fmaf(p1, v0, o[1][0]); o[1][1] = fmaf(p1, v1, o[1][1]);
            o[1][2] = fmaf(p1, v2, o[1][2]); o[1][3] = fmaf(p1, v3, o[1][3]);
            o[2][0] = fmaf(p2, v0, o[2][0]); o[2][1] = fmaf(p2, v1, o[2][1]);
            o[2][2] = fmaf(p2, v2, o[2][2]); o[2][3] = fmaf(p2, v3, o[2][3]);
            o[3][0] = fmaf(p3, v0, o[3][0]); o[3][1] = fmaf(p3, v1, o[3][1]);
            o[3][2] = fmaf(p3, v2, o[3][2]); o[3][3] = fmaf(p3, v3, o[3][3]);
        }
    }

#pragma unroll
    for (int i = 0; i < 4; i++) {
        float inv = 1.f / l[i];
        size_t row = (size_t)(b * SS + q0 + qg * 4 + i);
#pragma unroll
        for (int j = 0; j < 4; j++)
            CTX[row * EE + h * 64 + cg * 4 + j] = o[i][j] * inv;
    }
}

// ======================= LayerNorm =======================
__global__ __launch_bounds__(256) void ln_kernel(
    const float* __restrict__ in, const float* __restrict__ w,
    const float* __restrict__ b, float* __restrict__ out)
{
    int row = blockIdx.x;
    const float* x = in + (size_t)row * EE;
    int tid = threadIdx.x;

    float v[4], s = 0.f, sq = 0.f;
#pragma unroll
    for (int i = 0; i < 4; i++) {
        v[i] = x[tid + i * 256];
        s += v[i];
        sq += v[i] * v[i];
    }
#pragma unroll
    for (int off = 16; off > 0; off >>= 1) {
        s  += __shfl_xor_sync(0xffffffffu, s,  off);
        sq += __shfl_xor_sync(0xffffffffu, sq, off);
    }
    __shared__ float ss[8], ssq[8];
    if ((tid & 31) == 0) { ss[tid >> 5] = s; ssq[tid >> 5] = sq; }
    __syncthreads();
    float ts = 0.f, tsq = 0.f;
#pragma unroll
    for (int wi = 0; wi < 8; wi++) { ts += ss[wi]; tsq += ssq[wi]; }
    float mean = ts * (1.f / EE);
    float var = tsq * (1.f / EE) - mean * mean;
    float rstd = rsqrtf(var + 1e-12f);
    float* y = out + (size_t)row * EE;
#pragma unroll
    for (int i = 0; i < 4; i++) {
        int c = tid + i * 256;
        y[c] = (v[i] - mean) * rstd * w[c] + b[c];
    }
}

// ======================= launch =======================
extern "C" void kernel_launch(void* const* d_in, const int* in_sizes, int n_in,
                              void* d_out, int out_size)
{
    const float* x      = (const float*)d_in[0];
    const int*   am     = (const int*)d_in[1];
    const int*   tt     = (const int*)d_in[2];
    const float* w_qkv  = (const float*)d_in[3];
    const float* b_qkv  = (const float*)d_in[4];
    const float* w_out  = (const float*)d_in[5];
    const float* b_outp = (const float*)d_in[6];
    const float* ln_w   = (const float*)d_in[7];
    const float* ln_b   = (const float*)d_in[8];
    const float* w_in   = (const float*)d_in[9];
    const float* b_in   = (const float*)d_in[10];
    const float* w_ffo  = (const float*)d_in[11];
    const float* b_ffo  = (const float*)d_in[12];
    float* out = (float*)d_out;

    float *qkv, *ctx, *t1, *hb, *ffa, *t2, *wqkvT, *woutT, *winT, *wffoT;
    cudaGetSymbolAddress((void**)&qkv,   g_qkv);
    cudaGetSymbolAddress((void**)&ctx,   g_ctx);
    cudaGetSymbolAddress((void**)&t1,    g_t1);
    cudaGetSymbolAddress((void**)&hb,    g_h);
    cudaGetSymbolAddress((void**)&ffa,   g_ffa);
    cudaGetSymbolAddress((void**)&t2,    g_t2);
    cudaGetSymbolAddress((void**)&wqkvT, g_wqkvT);
    cudaGetSymbolAddress((void**)&woutT, g_woutT);
    cudaGetSymbolAddress((void**)&winT,  g_winT);
    cudaGetSymbolAddress((void**)&wffoT, g_wffoT);

    const int ATTN_SMEM = 3 * 64 * 65 * (int)sizeof(float);
    cudaFuncSetAttribute(attn_kernel, cudaFuncAttributeMaxDynamicSharedMemorySize, ATTN_SMEM);
    cudaFuncSetAttribute(mma_gemm, cudaFuncAttributeMaxDynamicSharedMemorySize, GEMM_SMEM_DYN);

    dim3 tb(32, 8);
    transpose_kernel<<<dim3(3 * EE / 32, EE / 32), tb>>>(w_qkv, wqkvT, EE, 3 * EE);
    transpose_kernel<<<dim3(EE / 32, EE / 32), tb>>>(w_out, woutT, EE, EE);
    transpose_kernel<<<dim3(FF / 32, EE / 32), tb>>>(w_in,  winT,  EE, FF);
    transpose_kernel<<<dim3(EE / 32, FF / 32), tb>>>(w_ffo, wffoT, FF, EE);

    mask_kernel<<<MR / 256, 256>>>(am, tt);

    // QKV projection
    mma_gemm<<<dim3(3 * EE / GBN, MR / GBM), 256, GEMM_SMEM_DYN>>>(
        x, wqkvT, b_qkv, nullptr, qkv, MR, 3 * EE, EE, 0);
    // attention
    attn_kernel<<<dim3(SS / 64, HH, BB), 256, ATTN_SMEM>>>(qkv, ctx);
    // out projection + residual
    mma_gemm<<<dim3(EE / GBN, MR / GBM), 256, GEMM_SMEM_DYN>>>(
        ctx, woutT, b_outp, x, t1, MR, EE, EE, 0);
    // LN -> h
    ln_kernel<<<MR, 256>>>(t1, ln_w, ln_b, hb);
    // FFN in + GELU
    mma_gemm<<<dim3(FF / GBN, MR / GBM), 256, GEMM_SMEM_DYN>>>(
        hb, winT, b_in, nullptr, ffa, MR, FF, EE, 1);
    // FFN out + residual
    mma_gemm<<<dim3(EE / GBN, MR / GBM), 256, GEMM_SMEM_DYN>>>(
        ffa, wffoT, b_ffo, hb, t2, MR, EE, FF, 0);
    // LN -> out
    ln_kernel<<<MR, 256>>>(t2, ln_w, ln_b, out);
}

// round 4
// speedup vs baseline: 3.0173x; 1.6604x over previous
#include <cuda_runtime.h>
#include <math.h>
#include <stdint.h>

// Problem constants
#define BB   8
#define SS   1024
#define EE   1024
#define HH   16
#define FF   4096
#define MR   (BB*SS)      // 8192 rows

// -------- scratch (static device globals; no runtime allocation) --------
__device__ float g_qkv[(size_t)MR * 3 * EE];
__device__ float g_ctx[(size_t)MR * EE];
__device__ float g_t1 [(size_t)MR * EE];
__device__ float g_h  [(size_t)MR * EE];
__device__ float g_ffa[(size_t)MR * FF];
__device__ float g_t2 [(size_t)MR * EE];
__device__ float g_kadd[MR];
__device__ float g_kneg[MR];
// transposed weights (tf32-rounded), [N,K] K-major
__device__ float g_wqkvT[(size_t)3 * EE * EE];
__device__ float g_woutT[(size_t)EE * EE];
__device__ float g_winT [(size_t)FF * EE];
__device__ float g_wffoT[(size_t)EE * FF];

// ======================= PTX helpers =======================
__device__ __forceinline__ uint32_t smem_u32(const void* p) {
    uint32_t a;
    asm("{ .reg .u64 t; cvta.to.shared.u64 t, %1; cvt.u32.u64 %0, t; }"
        : "=r"(a) : "l"(p));
    return a;
}
__device__ __forceinline__ void cp16(uint32_t dst, const void* src) {
    asm volatile("cp.async.cg.shared.global [%0], [%1], 16;" :: "r"(dst), "l"(src));
}
#define CP_COMMIT() asm volatile("cp.async.commit_group;" ::: "memory")

__device__ __forceinline__ void ldsm4(uint32_t& r0, uint32_t& r1, uint32_t& r2, uint32_t& r3,
                                      uint32_t addr) {
    asm volatile("ldmatrix.sync.aligned.m8n8.x4.shared.b16 {%0,%1,%2,%3}, [%4];"
                 : "=r"(r0), "=r"(r1), "=r"(r2), "=r"(r3) : "r"(addr));
}
__device__ __forceinline__ uint32_t f2tf32(uint32_t x) {
    uint32_t y;
    asm("cvt.rna.tf32.f32 %0, %1;" : "=r"(y) : "f"(__uint_as_float(x)));
    return y;
}
__device__ __forceinline__ void mma_tf32(float* c, const uint32_t* a, uint32_t b0, uint32_t b1) {
    asm volatile(
        "mma.sync.aligned.m16n8k8.row.col.f32.tf32.tf32.f32 "
        "{%0,%1,%2,%3}, {%4,%5,%6,%7}, {%8,%9}, {%0,%1,%2,%3};"
        : "+f"(c[0]), "+f"(c[1]), "+f"(c[2]), "+f"(c[3])
        : "r"(a[0]), "r"(a[1]), "r"(a[2]), "r"(a[3]), "r"(b0), "r"(b1));
}

// ======================= weight transpose + tf32 round =======================
__global__ void transpose_kernel(const float* __restrict__ W, float* __restrict__ WT,
                                 int K, int N) {
    __shared__ float t[32][33];
    int n0 = blockIdx.x * 32, k0 = blockIdx.y * 32;
    int tx = threadIdx.x, ty = threadIdx.y;
#pragma unroll
    for (int i = 0; i < 32; i += 8)
        t[ty + i][tx] = W[(size_t)(k0 + ty + i) * N + n0 + tx];
    __syncthreads();
#pragma unroll
    for (int i = 0; i < 32; i += 8) {
        float v = t[tx][ty + i];
        uint32_t b;
        asm("cvt.rna.tf32.f32 %0, %1;" : "=r"(b) : "f"(v));
        WT[(size_t)(n0 + ty + i) * K + k0 + tx] = __uint_as_float(b);
    }
}

// ======================= mask precompute =======================
__global__ void mask_kernel(const int* __restrict__ am, const int* __restrict__ tt) {
    int i = blockIdx.x * 256 + threadIdx.x;
    if (i >= MR) return;
    bool a  = (am[i] != 0);
    bool qm = (tt[i] == 1) || (!a) || ((i & (SS - 1)) == 0);
    g_kadd[i] = a  ? 1.f : 0.f;
    g_kneg[i] = qm ? 1.f : 0.f;
}

// ======================= tf32 tensor-core GEMM v2 =======================
// 512 threads, BM=128, BN=256, BK=32, 3 stages.
#define GBM 128
#define GBN 256
#define GBK 32
#define GSTAGE_A (GBM * GBK * 4)            // 16 KB
#define GSTAGE_B (GBN * GBK * 4)            // 32 KB
#define GSTAGE_BYTES (GSTAGE_A + GSTAGE_B)  // 48 KB
#define GEMM_SMEM_DYN (3 * GSTAGE_BYTES)    // 144 KB

__global__ __launch_bounds__(512, 1) void mma_gemm(
    const float* __restrict__ A, const float* __restrict__ BT,
    const float* __restrict__ bias, const float* __restrict__ res,
    float* __restrict__ C, int M, int N, int K, int act)
{
    extern __shared__ char dyn_smem[];
    uint32_t sbase = smem_u32(dyn_smem);
    int tid = threadIdx.x, lane = tid & 31, wid = tid >> 5;
    int wm = wid & 3, wn = wid >> 2;            // warp tile: rows wm*32, cols wn*64
    int bm = blockIdx.y * GBM, bn = blockIdx.x * GBN;

    float c[2][8][4];
#pragma unroll
    for (int mi = 0; mi < 2; mi++)
#pragma unroll
        for (int j = 0; j < 8; j++)
#pragma unroll
            for (int q = 0; q < 4; q++) c[mi][j][q] = 0.f;

    int T = K / GBK;

    auto load_tile = [&](int t, int s) {
        int k0 = t * GBK;
        uint32_t sA = sbase + s * GSTAGE_BYTES;
        uint32_t sB = sA + GSTAGE_A;
#pragma unroll
        for (int i = 0; i < 2; i++) {            // A: 1024 granules / 512 thr
            int g = tid + i * 512;
            int row = g >> 3, ch = g & 7;
            cp16(sA + row * 128 + ((ch ^ (row & 7)) << 4),
                 A + (size_t)(bm + row) * K + k0 + ch * 4);
        }
#pragma unroll
        for (int i = 0; i < 4; i++) {            // B: 2048 granules
            int g = tid + i * 512;
            int row = g >> 3, ch = g & 7;
            cp16(sB + row * 128 + ((ch ^ (row & 7)) << 4),
                 BT + (size_t)(bn + row) * K + k0 + ch * 4);
        }
    };

    load_tile(0, 0); CP_COMMIT();
    load_tile(1, 1); CP_COMMIT();

    int s_cur = 0, s_next = 2;
    for (int t = 0; t < T; t++) {
        asm volatile("cp.async.wait_group 1;" ::: "memory");
        __syncthreads();
        if (t + 2 < T) load_tile(t + 2, s_next);
        CP_COMMIT();

        uint32_t sA = sbase + s_cur * GSTAGE_BYTES;
        uint32_t sB = sA + GSTAGE_A;

#pragma unroll
        for (int p = 0; p < 2; p++) {            // two halves of BK=32
            // A fragments for both k-steps of this half (16 regs)
            uint32_t a[2][2][4];
#pragma unroll
            for (int mi = 0; mi < 2; mi++)
#pragma unroll
                for (int kk = 0; kk < 2; kk++) {
                    int ks = p * 2 + kk;
                    int r = wm * 32 + mi * 16 + ((lane >> 3) & 1) * 8 + (lane & 7);
                    int ch = ks * 2 + (lane >> 4);
                    ldsm4(a[mi][kk][0], a[mi][kk][1], a[mi][kk][2], a[mi][kk][3],
                          sA + r * 128 + ((ch ^ (r & 7)) << 4));
#pragma unroll
                    for (int q = 0; q < 4; q++) a[mi][kk][q] = f2tf32(a[mi][kk][q]);
                }
            // B fragment per n8 group, consumed immediately (4 live regs)
#pragma unroll
            for (int j = 0; j < 8; j++) {
                uint32_t b0, b1, b2, b3;
                int r = wn * 64 + j * 8 + (lane & 7);
                int ch = p * 4 + (lane >> 3);
                ldsm4(b0, b1, b2, b3, sB + r * 128 + ((ch ^ (r & 7)) << 4));
                mma_tf32(c[0][j], a[0][0], b0, b1);
                mma_tf32(c[1][j], a[1][0], b0, b1);
                mma_tf32(c[0][j], a[0][1], b2, b3);
                mma_tf32(c[1][j], a[1][1], b2, b3);
            }
        }
        s_cur = (s_cur == 2) ? 0 : s_cur + 1;
        s_next = (s_next == 2) ? 0 : s_next + 1;
    }

    // ---- epilogue ----
#pragma unroll
    for (int mi = 0; mi < 2; mi++) {
        int r0 = bm + wm * 32 + mi * 16 + (lane >> 2);
#pragma unroll
        for (int half = 0; half < 2; half++) {
            int r = r0 + half * 8;
            float* Crow = C + (size_t)r * N;
            const float* Rrow = res ? res + (size_t)r * N : nullptr;
#pragma unroll
            for (int j = 0; j < 8; j++) {
                int col = bn + wn * 64 + j * 8 + (lane & 3) * 2;
                float v0 = c[mi][j][half * 2 + 0] + bias[col];
                float v1 = c[mi][j][half * 2 + 1] + bias[col + 1];
                if (Rrow) { v0 += Rrow[col]; v1 += Rrow[col + 1]; }
                if (act) {
                    v0 = 0.5f * v0 * (1.0f + erff(v0 * 0.70710678118654752f));
                    v1 = 0.5f * v1 * (1.0f + erff(v1 * 0.70710678118654752f));
                }
                *(float2*)(Crow + col) = make_float2(v0, v1);
            }
        }
    }
}

// ======================= Flash attention (fp32 SIMT) =======================
__global__ __launch_bounds__(256) void attn_kernel(
    const float* __restrict__ QKV, float* __restrict__ CTX)
{
    extern __shared__ float sm[];
    float* sQ = sm;
    float* sK = sm + 64 * 65;
    float* sV = sm + 2 * 64 * 65;
    float* sP = sK;
    __shared__ float sAdd[64], sNeg[64], sAmq[64];

    int tid = threadIdx.x;
    int b = blockIdx.z, h = blockIdx.y, q0 = blockIdx.x * 64;

    const float* Qb = QKV + (size_t)b * SS * 3072 + h * 64;
    const float* Kb = Qb + 1024;
    const float* Vb = Qb + 2048;

    for (int i = tid; i < 64 * 64; i += 256) {
        int r = i >> 6, c = i & 63;
        sQ[r * 65 + c] = Qb[(size_t)(q0 + r) * 3072 + c];
    }
    for (int i = tid; i < 64; i += 256) sAmq[i] = g_kadd[b * SS + q0 + i];
    __syncthreads();

    int qg = tid >> 4;
    int cg = tid & 15;

    float amq[4];
#pragma unroll
    for (int i = 0; i < 4; i++) amq[i] = sAmq[qg * 4 + i];

    float m[4], l[4], o[4][4];
#pragma unroll
    for (int i = 0; i < 4; i++) {
        m[i] = -INFINITY; l[i] = 0.f;
#pragma unroll
        for (int j = 0; j < 4; j++) o[i][j] = 0.f;
    }

    const float* qp[4];
#pragma unroll
    for (int i = 0; i < 4; i++) qp[i] = &sQ[(qg * 4 + i) * 65];

    for (int k0 = 0; k0 < SS; k0 += 64) {
        __syncthreads();
        for (int i = tid; i < 64 * 64; i += 256) {
            int r = i >> 6, c = i & 63;
            sK[r * 65 + c] = Kb[(size_t)(k0 + r) * 3072 + c];
            sV[r * 65 + c] = Vb[(size_t)(k0 + r) * 3072 + c];
        }
        for (int i = tid; i < 64; i += 256) {
            sAdd[i] = g_kadd[b * SS + k0 + i];
            sNeg[i] = g_kneg[b * SS + k0 + i];
        }
        __syncthreads();

        float sc[4][4];
#pragma unroll
        for (int i = 0; i < 4; i++)
#pragma unroll
            for (int j = 0; j < 4; j++) sc[i][j] = 0.f;

        const float* kp[4];
#pragma unroll
        for (int j = 0; j < 4; j++) kp[j] = &sK[(cg * 4 + j) * 65];

#pragma unroll 8
        for (int d = 0; d < 64; d++) {
            float a0 = qp[0][d], a1 = qp[1][d], a2 = qp[2][d], a3 = qp[3][d];
            float b0 = kp[0][d], b1 = kp[1][d], b2 = kp[2][d], b3 = kp[3][d];
            sc[0][0] = fmaf(a0, b0, sc[0][0]); sc[0][1] = fmaf(a0, b1, sc[0][1]);
            sc[0][2] = fmaf(a0, b2, sc[0][2]); sc[0][3] = fmaf(a0, b3, sc[0][3]);
            sc[1][0] = fmaf(a1, b0, sc[1][0]); sc[1][1] = fmaf(a1, b1, sc[1][1]);
            sc[1][2] = fmaf(a1, b2, sc[1][2]); sc[1][3] = fmaf(a1, b3, sc[1][3]);
            sc[2][0] = fmaf(a2, b0, sc[2][0]); sc[2][1] = fmaf(a2, b1, sc[2][1]);
            sc[2][2] = fmaf(a2, b2, sc[2][2]); sc[2][3] = fmaf(a2, b3, sc[2][3]);
            sc[3][0] = fmaf(a3, b0, sc[3][0]); sc[3][1] = fmaf(a3, b1, sc[3][1]);
            sc[3][2] = fmaf(a3, b2, sc[3][2]); sc[3][3] = fmaf(a3, b3, sc[3][3]);
        }

        float kadd[4], kneg[4];
#pragma unroll
        for (int j = 0; j < 4; j++) { kadd[j] = sAdd[cg * 4 + j]; kneg[j] = sNeg[cg * 4 + j]; }
#pragma unroll
        for (int i = 0; i < 4; i++)
#pragma unroll
            for (int j = 0; j < 4; j++) {
                float v = sc[i][j] * 0.125f + amq[i] * kadd[j];
                sc[i][j] = (kneg[j] != 0.f) ? -1e30f : v;
            }

        float mt[4], lt[4], alpha[4];
#pragma unroll
        for (int i = 0; i < 4; i++) {
            mt[i] = fmaxf(fmaxf(sc[i][0], sc[i][1]), fmaxf(sc[i][2], sc[i][3]));
#pragma unroll
            for (int off = 8; off > 0; off >>= 1)
                mt[i] = fmaxf(mt[i], __shfl_xor_sync(0xffffffffu, mt[i], off, 16));
            float mn = fmaxf(m[i], mt[i]);
            alpha[i] = __expf(m[i] - mn);
            m[i] = mn;
            lt[i] = 0.f;
#pragma unroll
            for (int j = 0; j < 4; j++) {
                float p = __expf(sc[i][j] - mn);
                sc[i][j] = p;
                lt[i] += p;
            }
#pragma unroll
            for (int off = 8; off > 0; off >>= 1)
                lt[i] += __shfl_xor_sync(0xffffffffu, lt[i], off, 16);
            l[i] = l[i] * alpha[i] + lt[i];
#pragma unroll
            for (int j = 0; j < 4; j++) o[i][j] *= alpha[i];
        }

        __syncthreads();
#pragma unroll
        for (int i = 0; i < 4; i++)
#pragma unroll
            for (int j = 0; j < 4; j++)
                sP[(qg * 4 + i) * 65 + cg * 4 + j] = sc[i][j];
        __syncthreads();

        const float* pp[4];
#pragma unroll
        for (int i = 0; i < 4; i++) pp[i] = &sP[(qg * 4 + i) * 65];
#pragma unroll 8
        for (int k = 0; k < 64; k++) {
            const float* vp = &sV[k * 65 + cg * 4];
            float v0 = vp[0], v1 = vp[1], v2 = vp[2], v3 = vp[3];
            float p0 = pp[0][k], p1 = pp[1][k], p2 = pp[2][k], p3 = pp[3][k];
            o[0][0] = fmaf(p0, v0, o[0][0]); o[0][1] = fmaf(p0, v1, o[0][1]);
            o[0][2] = fmaf(p0, v2, o[0][2]); o[0][3] = fmaf(p0, v3, o[0][3]);
            o[1][0] = fmaf(p1, v0, o[1][0]); o[1][1] = fmaf(p1, v1, o[1][1]);
            o[1][2] = fmaf(p1, v2, o[1][2]); o[1][3] = fmaf(p1, v3, o[1][3]);
            o[2][0] = fmaf(p2, v0, o[2][0]); o[2][1] = fmaf(p2, v1, o[2][1]);
            o[2][2] = fmaf(p2, v2, o[2][2]); o[2][3] = fmaf(p2, v3, o[2][3]);
            o[3][0] = fmaf(p3, v0, o[3][0]); o[3][1] = fmaf(p3, v1, o[3][1]);
            o[3][2] = fmaf(p3, v2, o[3][2]); o[3][3] = fmaf(p3, v3, o[3][3]);
        }
    }

#pragma unroll
    for (int i = 0; i < 4; i++) {
        float inv = 1.f / l[i];
        size_t row = (size_t)(b * SS + q0 + qg * 4 + i);
#pragma unroll
        for (int j = 0; j < 4; j++)
            CTX[row * EE + h * 64 + cg * 4 + j] = o[i][j] * inv;
    }
}

// ======================= LayerNorm =======================
__global__ __launch_bounds__(256) void ln_kernel(
    const float* __restrict__ in, const float* __restrict__ w,
    const float* __restrict__ b, float* __restrict__ out)
{
    int row = blockIdx.x;
    const float* x = in + (size_t)row * EE;
    int tid = threadIdx.x;

    float v[4], s = 0.f, sq = 0.f;
#pragma unroll
    for (int i = 0; i < 4; i++) {
        v[i] = x[tid + i * 256];
        s += v[i];
        sq += v[i] * v[i];
    }
#pragma unroll
    for (int off = 16; off > 0; off >>= 1) {
        s  += __shfl_xor_sync(0xffffffffu, s,  off);
        sq += __shfl_xor_sync(0xffffffffu, sq, off);
    }
    __shared__ float ss[8], ssq[8];
    if ((tid & 31) == 0) { ss[tid >> 5] = s; ssq[tid >> 5] = sq; }
    __syncthreads();
    float ts = 0.f, tsq = 0.f;
#pragma unroll
    for (int wi = 0; wi < 8; wi++) { ts += ss[wi]; tsq += ssq[wi]; }
    float mean = ts * (1.f / EE);
    float var = tsq * (1.f / EE) - mean * mean;
    float rstd = rsqrtf(var + 1e-12f);
    float* y = out + (size_t)row * EE;
#pragma unroll
    for (int i = 0; i < 4; i++) {
        int c = tid + i * 256;
        y[c] = (v[i] - mean) * rstd * w[c] + b[c];
    }
}

// ======================= launch =======================
extern "C" void kernel_launch(void* const* d_in, const int* in_sizes, int n_in,
                              void* d_out, int out_size)
{
    const float* x      = (const float*)d_in[0];
    const int*   am     = (const int*)d_in[1];
    const int*   tt     = (const int*)d_in[2];
    const float* w_qkv  = (const float*)d_in[3];
    const float* b_qkv  = (const float*)d_in[4];
    const float* w_out  = (const float*)d_in[5];
    const float* b_outp = (const float*)d_in[6];
    const float* ln_w   = (const float*)d_in[7];
    const float* ln_b   = (const float*)d_in[8];
    const float* w_in   = (const float*)d_in[9];
    const float* b_in   = (const float*)d_in[10];
    const float* w_ffo  = (const float*)d_in[11];
    const float* b_ffo  = (const float*)d_in[12];
    float* out = (float*)d_out;

    float *qkv, *ctx, *t1, *hb, *ffa, *t2, *wqkvT, *woutT, *winT, *wffoT;
    cudaGetSymbolAddress((void**)&qkv,   g_qkv);
    cudaGetSymbolAddress((void**)&ctx,   g_ctx);
    cudaGetSymbolAddress((void**)&t1,    g_t1);
    cudaGetSymbolAddress((void**)&hb,    g_h);
    cudaGetSymbolAddress((void**)&ffa,   g_ffa);
    cudaGetSymbolAddress((void**)&t2,    g_t2);
    cudaGetSymbolAddress((void**)&wqkvT, g_wqkvT);
    cudaGetSymbolAddress((void**)&woutT, g_woutT);
    cudaGetSymbolAddress((void**)&winT,  g_winT);
    cudaGetSymbolAddress((void**)&wffoT, g_wffoT);

    const int ATTN_SMEM = 3 * 64 * 65 * (int)sizeof(float);
    cudaFuncSetAttribute(attn_kernel, cudaFuncAttributeMaxDynamicSharedMemorySize, ATTN_SMEM);
    cudaFuncSetAttribute(mma_gemm, cudaFuncAttributeMaxDynamicSharedMemorySize, GEMM_SMEM_DYN);

    dim3 tb(32, 8);
    transpose_kernel<<<dim3(3 * EE / 32, EE / 32), tb>>>(w_qkv, wqkvT, EE, 3 * EE);
    transpose_kernel<<<dim3(EE / 32, EE / 32), tb>>>(w_out, woutT, EE, EE);
    transpose_kernel<<<dim3(FF / 32, EE / 32), tb>>>(w_in,  winT,  EE, FF);
    transpose_kernel<<<dim3(EE / 32, FF / 32), tb>>>(w_ffo, wffoT, FF, EE);

    mask_kernel<<<MR / 256, 256>>>(am, tt);

    // QKV projection
    mma_gemm<<<dim3(3 * EE / GBN, MR / GBM), 512, GEMM_SMEM_DYN>>>(
        x, wqkvT, b_qkv, nullptr, qkv, MR, 3 * EE, EE, 0);
    // attention
    attn_kernel<<<dim3(SS / 64, HH, BB), 256, ATTN_SMEM>>>(qkv, ctx);
    // out projection + residual
    mma_gemm<<<dim3(EE / GBN, MR / GBM), 512, GEMM_SMEM_DYN>>>(
        ctx, woutT, b_outp, x, t1, MR, EE, EE, 0);
    // LN -> h
    ln_kernel<<<MR, 256>>>(t1, ln_w, ln_b, hb);
    // FFN in + GELU
    mma_gemm<<<dim3(FF / GBN, MR / GBM), 512, GEMM_SMEM_DYN>>>(
        hb, winT, b_in, nullptr, ffa, MR, FF, EE, 1);
    // FFN out + residual
    mma_gemm<<<dim3(EE / GBN, MR / GBM), 512, GEMM_SMEM_DYN>>>(
        ffa, wffoT, b_ffo, hb, t2, MR, EE, FF, 0);
    // LN -> out
    ln_kernel<<<MR, 256>>>(t2, ln_w, ln_b, out);
}

// round 7
// speedup vs baseline: 3.6809x; 1.2199x over previous
#include <cuda_runtime.h>
#include <math.h>
#include <stdint.h>

// Problem constants
#define BB   8
#define SS   1024
#define EE   1024
#define HH   16
#define FF   4096
#define MR   (BB*SS)      // 8192 rows

// -------- scratch (static device globals; no runtime allocation) --------
__device__ float g_qkv[(size_t)MR * 3 * EE];
__device__ float g_ctx[(size_t)MR * EE];
__device__ float g_t1 [(size_t)MR * EE];
__device__ float g_h  [(size_t)MR * EE];
__device__ float g_ffa[(size_t)MR * FF];
__device__ float g_t2 [(size_t)MR * EE];
__device__ float g_kadd[MR];
__device__ float g_kneg[MR];
__device__ float g_wqkvT[(size_t)3 * EE * EE];
__device__ float g_woutT[(size_t)EE * EE];
__device__ float g_winT [(size_t)FF * EE];
__device__ float g_wffoT[(size_t)EE * FF];

// ======================= PTX helpers =======================
__device__ __forceinline__ uint32_t smem_u32(const void* p) {
    uint32_t a;
    asm("{ .reg .u64 t; cvta.to.shared.u64 t, %1; cvt.u32.u64 %0, t; }"
        : "=r"(a) : "l"(p));
    return a;
}
__device__ __forceinline__ void cp16(uint32_t dst, const void* src) {
    asm volatile("cp.async.cg.shared.global [%0], [%1], 16;" :: "r"(dst), "l"(src));
}
#define CP_COMMIT() asm volatile("cp.async.commit_group;" ::: "memory")

__device__ __forceinline__ void ldsm4(uint32_t& r0, uint32_t& r1, uint32_t& r2, uint32_t& r3,
                                      uint32_t addr) {
    asm volatile("ldmatrix.sync.aligned.m8n8.x4.shared.b16 {%0,%1,%2,%3}, [%4];"
                 : "=r"(r0), "=r"(r1), "=r"(r2), "=r"(r3) : "r"(addr));
}
__device__ __forceinline__ uint32_t f2tf32(uint32_t x) {
    uint32_t y;
    asm("cvt.rna.tf32.f32 %0, %1;" : "=r"(y) : "f"(__uint_as_float(x)));
    return y;
}
__device__ __forceinline__ void mma_tf32(float* c, const uint32_t* a, uint32_t b0, uint32_t b1) {
    asm volatile(
        "mma.sync.aligned.m16n8k8.row.col.f32.tf32.tf32.f32 "
        "{%0,%1,%2,%3}, {%4,%5,%6,%7}, {%8,%9}, {%0,%1,%2,%3};"
        : "+f"(c[0]), "+f"(c[1]), "+f"(c[2]), "+f"(c[3])
        : "r"(a[0]), "r"(a[1]), "r"(a[2]), "r"(a[3]), "r"(b0), "r"(b1));
}

// ======================= weight transpose + tf32 round =======================
__global__ void transpose_kernel(const float* __restrict__ W, float* __restrict__ WT,
                                 int K, int N) {
    __shared__ float t[32][33];
    int n0 = blockIdx.x * 32, k0 = blockIdx.y * 32;
    int tx = threadIdx.x, ty = threadIdx.y;
#pragma unroll
    for (int i = 0; i < 32; i += 8)
        t[ty + i][tx] = W[(size_t)(k0 + ty + i) * N + n0 + tx];
    __syncthreads();
#pragma unroll
    for (int i = 0; i < 32; i += 8) {
        float v = t[tx][ty + i];
        uint32_t b;
        asm("cvt.rna.tf32.f32 %0, %1;" : "=r"(b) : "f"(v));
        WT[(size_t)(n0 + ty + i) * K + k0 + tx] = __uint_as_float(b);
    }
}

// ======================= mask precompute =======================
__global__ void mask_kernel(const int* __restrict__ am, const int* __restrict__ tt) {
    int i = blockIdx.x * 256 + threadIdx.x;
    if (i >= MR) return;
    bool a  = (am[i] != 0);
    bool qm = (tt[i] == 1) || (!a) || ((i & (SS - 1)) == 0);
    g_kadd[i] = a  ? 1.f : 0.f;
    g_kneg[i] = qm ? 1.f : 0.f;
}

// ======================= tf32 tensor-core GEMM (unchanged from R4) =======================
#define GBM 128
#define GBN 256
#define GBK 32
#define GSTAGE_A (GBM * GBK * 4)
#define GSTAGE_B (GBN * GBK * 4)
#define GSTAGE_BYTES (GSTAGE_A + GSTAGE_B)
#define GEMM_SMEM_DYN (3 * GSTAGE_BYTES)

__global__ __launch_bounds__(512, 1) void mma_gemm(
    const float* __restrict__ A, const float* __restrict__ BT,
    const float* __restrict__ bias, const float* __restrict__ res,
    float* __restrict__ C, int M, int N, int K, int act)
{
    extern __shared__ char dyn_smem[];
    uint32_t sbase = smem_u32(dyn_smem);
    int tid = threadIdx.x, lane = tid & 31, wid = tid >> 5;
    int wm = wid & 3, wn = wid >> 2;
    int bm = blockIdx.y * GBM, bn = blockIdx.x * GBN;

    float c[2][8][4];
#pragma unroll
    for (int mi = 0; mi < 2; mi++)
#pragma unroll
        for (int j = 0; j < 8; j++)
#pragma unroll
            for (int q = 0; q < 4; q++) c[mi][j][q] = 0.f;

    int T = K / GBK;

    auto load_tile = [&](int t, int s) {
        int k0 = t * GBK;
        uint32_t sA = sbase + s * GSTAGE_BYTES;
        uint32_t sB = sA + GSTAGE_A;
#pragma unroll
        for (int i = 0; i < 2; i++) {
            int g = tid + i * 512;
            int row = g >> 3, ch = g & 7;
            cp16(sA + row * 128 + ((ch ^ (row & 7)) << 4),
                 A + (size_t)(bm + row) * K + k0 + ch * 4);
        }
#pragma unroll
        for (int i = 0; i < 4; i++) {
            int g = tid + i * 512;
            int row = g >> 3, ch = g & 7;
            cp16(sB + row * 128 + ((ch ^ (row & 7)) << 4),
                 BT + (size_t)(bn + row) * K + k0 + ch * 4);
        }
    };

    load_tile(0, 0); CP_COMMIT();
    load_tile(1, 1); CP_COMMIT();

    int s_cur = 0, s_next = 2;
    for (int t = 0; t < T; t++) {
        asm volatile("cp.async.wait_group 1;" ::: "memory");
        __syncthreads();
        if (t + 2 < T) load_tile(t + 2, s_next);
        CP_COMMIT();

        uint32_t sA = sbase + s_cur * GSTAGE_BYTES;
        uint32_t sB = sA + GSTAGE_A;

#pragma unroll
        for (int p = 0; p < 2; p++) {
            uint32_t a[2][2][4];
#pragma unroll
            for (int mi = 0; mi < 2; mi++)
#pragma unroll
                for (int kk = 0; kk < 2; kk++) {
                    int ks = p * 2 + kk;
                    int r = wm * 32 + mi * 16 + ((lane >> 3) & 1) * 8 + (lane & 7);
                    int ch = ks * 2 + (lane >> 4);
                    ldsm4(a[mi][kk][0], a[mi][kk][1], a[mi][kk][2], a[mi][kk][3],
                          sA + r * 128 + ((ch ^ (r & 7)) << 4));
#pragma unroll
                    for (int q = 0; q < 4; q++) a[mi][kk][q] = f2tf32(a[mi][kk][q]);
                }
#pragma unroll
            for (int j = 0; j < 8; j++) {
                uint32_t b0, b1, b2, b3;
                int r = wn * 64 + j * 8 + (lane & 7);
                int ch = p * 4 + (lane >> 3);
                ldsm4(b0, b1, b2, b3, sB + r * 128 + ((ch ^ (r & 7)) << 4));
                mma_tf32(c[0][j], a[0][0], b0, b1);
                mma_tf32(c[1][j], a[1][0], b0, b1);
                mma_tf32(c[0][j], a[0][1], b2, b3);
                mma_tf32(c[1][j], a[1][1], b2, b3);
            }
        }
        s_cur = (s_cur == 2) ? 0 : s_cur + 1;
        s_next = (s_next == 2) ? 0 : s_next + 1;
    }

#pragma unroll
    for (int mi = 0; mi < 2; mi++) {
        int r0 = bm + wm * 32 + mi * 16 + (lane >> 2);
#pragma unroll
        for (int half = 0; half < 2; half++) {
            int r = r0 + half * 8;
            float* Crow = C + (size_t)r * N;
            const float* Rrow = res ? res + (size_t)r * N : nullptr;
#pragma unroll
            for (int j = 0; j < 8; j++) {
                int col = bn + wn * 64 + j * 8 + (lane & 3) * 2;
                float v0 = c[mi][j][half * 2 + 0] + bias[col];
                float v1 = c[mi][j][half * 2 + 1] + bias[col + 1];
                if (Rrow) { v0 += Rrow[col]; v1 += Rrow[col + 1]; }
                if (act) {
                    v0 = 0.5f * v0 * (1.0f + erff(v0 * 0.70710678118654752f));
                    v1 = 0.5f * v1 * (1.0f + erff(v1 * 0.70710678118654752f));
                }
                *(float2*)(Crow + col) = make_float2(v0, v1);
            }
        }
    }
}

// ======================= Flash attention with tf32 mma.sync =======================
// 256 threads / 8 warps. BQ=128 q rows, BK=64 keys/tile, HD=64.
// smem rows padded to 68 floats (272 B = 17*16B): 16B-aligned ldmatrix rows,
// natural bank skew (no XOR swizzle needed).
#define AQ 128
#define AK 64
#define APITCH 68
#define ATTN_SMEM_DYN ((AQ * APITCH + AK * APITCH + AK * APITCH + AQ * APITCH) * 4)

__global__ __launch_bounds__(256, 2) void attn_mma(
    const float* __restrict__ QKV, float* __restrict__ CTX)
{
    extern __shared__ float as[];
    float* sQ  = as;                           // 128 x 68
    float* sK  = sQ + AQ * APITCH;             // 64 x 68
    float* sVT = sK + AK * APITCH;             // 64 x 68 (V transposed: [d][k])
    float* sP  = sVT + AK * APITCH;            // 128 x 68
    __shared__ float sAdd[AK], sNeg[AK];

    uint32_t uQ = smem_u32(sQ), uK = smem_u32(sK), uVT = smem_u32(sVT), uP = smem_u32(sP);

    int tid = threadIdx.x, lane = tid & 31, wid = tid >> 5;
    int b = blockIdx.z, h = blockIdx.y, q0 = blockIdx.x * AQ;
    int wq0 = wid * 16;                        // warp's q band within tile

    const float* Qb = QKV + (size_t)b * SS * 3072 + h * 64;
    const float* Kb = Qb + 1024;
    const float* Vb = Qb + 2048;

    // ---- load Q tile (once) ----
    for (int i = tid; i < AQ * 16; i += 256) {
        int r = i >> 4, c4 = i & 15;
        float4 v = *(const float4*)(Qb + (size_t)(q0 + r) * 3072 + c4 * 4);
        *(float4*)(sQ + r * APITCH + c4 * 4) = v;
    }

    // per-row q mask values (additive-mask row term)
    int lr = lane >> 2;
    float amq0 = g_kadd[b * SS + q0 + wq0 + lr];
    float amq1 = g_kadd[b * SS + q0 + wq0 + lr + 8];

    float m0 = -INFINITY, m1 = -INFINITY, l0 = 0.f, l1 = 0.f;
    float o[8][4];
#pragma unroll
    for (int j = 0; j < 8; j++)
#pragma unroll
        for (int q = 0; q < 4; q++) o[j][q] = 0.f;

    int sub = lane & 3, baselane = lane & ~3;

    for (int k0 = 0; k0 < SS; k0 += AK) {
        __syncthreads();   // previous tile fully consumed before overwrite

        // ---- load K tile [64 keys][64 d] ----
        for (int i = tid; i < AK * 16; i += 256) {
            int r = i >> 4, c4 = i & 15;
            float4 v = *(const float4*)(Kb + (size_t)(k0 + r) * 3072 + c4 * 4);
            *(float4*)(sK + r * APITCH + c4 * 4) = v;
        }
        // ---- load V tile transposed into sVT[d][k] via 4-lane SOA transpose ----
#pragma unroll
        for (int it = 0; it < 4; it++) {
            int g = tid >> 2;
            int cch = g & 15;                     // d chunk (4 floats)
            int kb = ((g >> 4) << 2) + (it << 4); // key base (float4 of k)
            float4 v = *(const float4*)(Vb + (size_t)(k0 + kb + sub) * 3072 + cch * 4);
            float a0 = v.x, a1 = v.y, a2 = v.z, a3 = v.w;
            float t0, t1, t2, t3;
#pragma unroll
            for (int j = 0; j < 4; j++) {
                int sidx = (sub + j) & 3;
                float sval = sidx == 0 ? a0 : sidx == 1 ? a1 : sidx == 2 ? a2 : a3;
                int i = (sub - j) & 3;
                float r = __shfl_sync(0xffffffffu, sval, baselane | i);
                if (i == 0) t0 = r; else if (i == 1) t1 = r; else if (i == 2) t2 = r; else t3 = r;
            }
            int d = cch * 4 + sub;
            *(float4*)(sVT + d * APITCH + kb) = make_float4(t0, t1, t2, t3);
        }
        // ---- per-key mask values ----
        if (tid < AK) {
            sAdd[tid] = g_kadd[b * SS + k0 + tid];
            sNeg[tid] = g_kneg[b * SS + k0 + tid];
        }
        __syncthreads();

        // ================= S = Q @ K^T =================
        float c[8][4];
#pragma unroll
        for (int j = 0; j < 8; j++)
#pragma unroll
            for (int q = 0; q < 4; q++) c[j][q] = 0.f;

#pragma unroll
        for (int p = 0; p < 4; p++) {            // d = 64 -> 4 pairs of k8 steps
            uint32_t a[2][4];
#pragma unroll
            for (int kk = 0; kk < 2; kk++) {
                int ks = p * 2 + kk;
                int r = wq0 + ((lane >> 3) & 1) * 8 + (lane & 7);
                int ch = ks * 2 + (lane >> 4);
                ldsm4(a[kk][0], a[kk][1], a[kk][2], a[kk][3],
                      uQ + r * (APITCH * 4) + ch * 16);
#pragma unroll
                for (int q = 0; q < 4; q++) a[kk][q] = f2tf32(a[kk][q]);
            }
#pragma unroll
            for (int j = 0; j < 8; j++) {
                uint32_t b0, b1, b2, b3;
                int r = j * 8 + (lane & 7);
                int ch = p * 4 + (lane >> 3);
                ldsm4(b0, b1, b2, b3, uK + r * (APITCH * 4) + ch * 16);
                b0 = f2tf32(b0); b1 = f2tf32(b1); b2 = f2tf32(b2); b3 = f2tf32(b3);
                mma_tf32(c[j], a[0], b0, b1);
                mma_tf32(c[j], a[1], b2, b3);
            }
        }

        // ================= mask + online softmax =================
        float mt0 = -INFINITY, mt1 = -INFINITY;
#pragma unroll
        for (int j = 0; j < 8; j++) {
            int col = j * 8 + sub * 2;
            float ka0 = sAdd[col], ka1 = sAdd[col + 1];
            float kn0 = sNeg[col], kn1 = sNeg[col + 1];
            c[j][0] = (kn0 != 0.f) ? -1e30f : c[j][0] * 0.125f + amq0 * ka0;
            c[j][1] = (kn1 != 0.f) ? -1e30f : c[j][1] * 0.125f + amq0 * ka1;
            c[j][2] = (kn0 != 0.f) ? -1e30f : c[j][2] * 0.125f + amq1 * ka0;
            c[j][3] = (kn1 != 0.f) ? -1e30f : c[j][3] * 0.125f + amq1 * ka1;
            mt0 = fmaxf(mt0, fmaxf(c[j][0], c[j][1]));
            mt1 = fmaxf(mt1, fmaxf(c[j][2], c[j][3]));
        }
        mt0 = fmaxf(mt0, __shfl_xor_sync(0xffffffffu, mt0, 1));
        mt0 = fmaxf(mt0, __shfl_xor_sync(0xffffffffu, mt0, 2));
        mt1 = fmaxf(mt1, __shfl_xor_sync(0xffffffffu, mt1, 1));
        mt1 = fmaxf(mt1, __shfl_xor_sync(0xffffffffu, mt1, 2));

        float mn0 = fmaxf(m0, mt0), mn1 = fmaxf(m1, mt1);
        float alpha0 = __expf(m0 - mn0), alpha1 = __expf(m1 - mn1);
        m0 = mn0; m1 = mn1;

        float s0 = 0.f, s1 = 0.f;
#pragma unroll
        for (int j = 0; j < 8; j++) {
            c[j][0] = __expf(c[j][0] - mn0);
            c[j][1] = __expf(c[j][1] - mn0);
            c[j][2] = __expf(c[j][2] - mn1);
            c[j][3] = __expf(c[j][3] - mn1);
            s0 += c[j][0] + c[j][1];
            s1 += c[j][2] + c[j][3];
        }
        s0 += __shfl_xor_sync(0xffffffffu, s0, 1);
        s0 += __shfl_xor_sync(0xffffffffu, s0, 2);
        s1 += __shfl_xor_sync(0xffffffffu, s1, 1);
        s1 += __shfl_xor_sync(0xffffffffu, s1, 2);
        l0 = l0 * alpha0 + s0;
        l1 = l1 * alpha1 + s1;

#pragma unroll
        for (int j = 0; j < 8; j++) {
            o[j][0] *= alpha0; o[j][1] *= alpha0;
            o[j][2] *= alpha1; o[j][3] *= alpha1;
        }

        // ---- store P into warp-private band of sP (warp-local sync only) ----
#pragma unroll
        for (int j = 0; j < 8; j++) {
            int col = j * 8 + sub * 2;
            *(float2*)(sP + (wq0 + lr) * APITCH + col)     = make_float2(c[j][0], c[j][1]);
            *(float2*)(sP + (wq0 + lr + 8) * APITCH + col) = make_float2(c[j][2], c[j][3]);
        }
        __syncwarp();

        // ================= O += P @ V =================
#pragma unroll
        for (int p = 0; p < 4; p++) {            // keys = 64 -> 4 pairs of k8 steps
            uint32_t a[2][4];
#pragma unroll
            for (int kk = 0; kk < 2; kk++) {
                int ks = p * 2 + kk;
                int r = wq0 + ((lane >> 3) & 1) * 8 + (lane & 7);
                int ch = ks * 2 + (lane >> 4);
                ldsm4(a[kk][0], a[kk][1], a[kk][2], a[kk][3],
                      uP + r * (APITCH * 4) + ch * 16);
#pragma unroll
                for (int q = 0; q < 4; q++) a[kk][q] = f2tf32(a[kk][q]);
            }
#pragma unroll
            for (int j = 0; j < 8; j++) {        // d n-tiles
                uint32_t b0, b1, b2, b3;
                int r = j * 8 + (lane & 7);
                int ch = p * 4 + (lane >> 3);
                ldsm4(b0, b1, b2, b3, uVT + r * (APITCH * 4) + ch * 16);
                b0 = f2tf32(b0); b1 = f2tf32(b1); b2 = f2tf32(b2); b3 = f2tf32(b3);
                mma_tf32(o[j], a[0], b0, b1);
                mma_tf32(o[j], a[1], b2, b3);
            }
        }
    }

    // ---- epilogue ----
    float inv0 = 1.f / l0, inv1 = 1.f / l1;
    size_t row0 = (size_t)(b * SS + q0 + wq0 + lr);
    size_t row1 = row0 + 8;
#pragma unroll
    for (int j = 0; j < 8; j++) {
        int col = h * 64 + j * 8 + sub * 2;
        *(float2*)(CTX + row0 * EE + col) = make_float2(o[j][0] * inv0, o[j][1] * inv0);
        *(float2*)(CTX + row1 * EE + col) = make_float2(o[j][2] * inv1, o[j][3] * inv1);
    }
}

// ======================= LayerNorm =======================
__global__ __launch_bounds__(256) void ln_kernel(
    const float* __restrict__ in, const float* __restrict__ w,
    const float* __restrict__ b, float* __restrict__ out)
{
    int row = blockIdx.x;
    const float* x = in + (size_t)row * EE;
    int tid = threadIdx.x;

    float v[4], s = 0.f, sq = 0.f;
#pragma unroll
    for (int i = 0; i < 4; i++) {
        v[i] = x[tid + i * 256];
        s += v[i];
        sq += v[i] * v[i];
    }
#pragma unroll
    for (int off = 16; off > 0; off >>= 1) {
        s  += __shfl_xor_sync(0xffffffffu, s,  off);
        sq += __shfl_xor_sync(0xffffffffu, sq, off);
    }
    __shared__ float ss[8], ssq[8];
    if ((tid & 31) == 0) { ss[tid >> 5] = s; ssq[tid >> 5] = sq; }
    __syncthreads();
    float ts = 0.f, tsq = 0.f;
#pragma unroll
    for (int wi = 0; wi < 8; wi++) { ts += ss[wi]; tsq += ssq[wi]; }
    float mean = ts * (1.f / EE);
    float var = tsq * (1.f / EE) - mean * mean;
    float rstd = rsqrtf(var + 1e-12f);
    float* y = out + (size_t)row * EE;
#pragma unroll
    for (int i = 0; i < 4; i++) {
        int c = tid + i * 256;
        y[c] = (v[i] - mean) * rstd * w[c] + b[c];
    }
}

// ======================= launch =======================
extern "C" void kernel_launch(void* const* d_in, const int* in_sizes, int n_in,
                              void* d_out, int out_size)
{
    const float* x      = (const float*)d_in[0];
    const int*   am     = (const int*)d_in[1];
    const int*   tt     = (const int*)d_in[2];
    const float* w_qkv  = (const float*)d_in[3];
    const float* b_qkv  = (const float*)d_in[4];
    const float* w_out  = (const float*)d_in[5];
    const float* b_outp = (const float*)d_in[6];
    const float* ln_w   = (const float*)d_in[7];
    const float* ln_b   = (const float*)d_in[8];
    const float* w_in   = (const float*)d_in[9];
    const float* b_in   = (const float*)d_in[10];
    const float* w_ffo  = (const float*)d_in[11];
    const float* b_ffo  = (const float*)d_in[12];
    float* out = (float*)d_out;

    float *qkv, *ctx, *t1, *hb, *ffa, *t2, *wqkvT, *woutT, *winT, *wffoT;
    cudaGetSymbolAddress((void**)&qkv,   g_qkv);
    cudaGetSymbolAddress((void**)&ctx,   g_ctx);
    cudaGetSymbolAddress((void**)&t1,    g_t1);
    cudaGetSymbolAddress((void**)&hb,    g_h);
    cudaGetSymbolAddress((void**)&ffa,   g_ffa);
    cudaGetSymbolAddress((void**)&t2,    g_t2);
    cudaGetSymbolAddress((void**)&wqkvT, g_wqkvT);
    cudaGetSymbolAddress((void**)&woutT, g_woutT);
    cudaGetSymbolAddress((void**)&winT,  g_winT);
    cudaGetSymbolAddress((void**)&wffoT, g_wffoT);

    cudaFuncSetAttribute(attn_mma, cudaFuncAttributeMaxDynamicSharedMemorySize, ATTN_SMEM_DYN);
    cudaFuncSetAttribute(mma_gemm, cudaFuncAttributeMaxDynamicSharedMemorySize, GEMM_SMEM_DYN);

    dim3 tb(32, 8);
    transpose_kernel<<<dim3(3 * EE / 32, EE / 32), tb>>>(w_qkv, wqkvT, EE, 3 * EE);
    transpose_kernel<<<dim3(EE / 32, EE / 32), tb>>>(w_out, woutT, EE, EE);
    transpose_kernel<<<dim3(FF / 32, EE / 32), tb>>>(w_in,  winT,  EE, FF);
    transpose_kernel<<<dim3(EE / 32, FF / 32), tb>>>(w_ffo, wffoT, FF, EE);

    mask_kernel<<<MR / 256, 256>>>(am, tt);

    // QKV projection
    mma_gemm<<<dim3(3 * EE / GBN, MR / GBM), 512, GEMM_SMEM_DYN>>>(
        x, wqkvT, b_qkv, nullptr, qkv, MR, 3 * EE, EE, 0);
    // attention (tensor-core flash)
    attn_mma<<<dim3(SS / AQ, HH, BB), 256, ATTN_SMEM_DYN>>>(qkv, ctx);
    // out projection + residual
    mma_gemm<<<dim3(EE / GBN, MR / GBM), 512, GEMM_SMEM_DYN>>>(
        ctx, woutT, b_outp, x, t1, MR, EE, EE, 0);
    // LN -> h
    ln_kernel<<<MR, 256>>>(t1, ln_w, ln_b, hb);
    // FFN in + GELU
    mma_gemm<<<dim3(FF / GBN, MR / GBM), 512, GEMM_SMEM_DYN>>>(
        hb, winT, b_in, nullptr, ffa, MR, FF, EE, 1);
    // FFN out + residual
    mma_gemm<<<dim3(EE / GBN, MR / GBM), 512, GEMM_SMEM_DYN>>>(
        ffa, wffoT, b_ffo, hb, t2, MR, EE, FF, 0);
    // LN -> out
    ln_kernel<<<MR, 256>>>(t2, ln_w, ln_b, out);
}